// round 1
// baseline (speedup 1.0000x reference)
#include <cuda_runtime.h>
#include <math.h>
#include <stdint.h>

// Problem constants (fixed by the reference setup)
#define NN 100000
#define EE 1600000
#define HH 128

// ----------------------------------------------------------------------------
// Scratch (device globals; allocation inside kernel_launch is forbidden)
// ----------------------------------------------------------------------------
__device__ float g_h   [(size_t)NN * 256];  // cell output (concat of h1|h2)
__device__ float g_hpre[(size_t)NN * 128];  // pre-linear output
__device__ float g_t   [(size_t)NN * 128];  // h_pre @ arma_w
__device__ float g_u   [(size_t)NN * 128];  // h_pre @ arma_v + arma_b
__device__ float g_r   [(size_t)NN * 128];  // h_pre @ sage_wr + sage_bl
__device__ float g_agg [(size_t)NN * 128];  // ARMA neighborhood sum
__device__ float g_s   [(size_t)NN * 128];  // SAGE weighted sum
__device__ float g_deg [NN];
__device__ float g_cnt [NN];
__device__ float g_dinv[NN];
__device__ float g_icnt[NN];

// ----------------------------------------------------------------------------
// Utility: zero a float buffer (float4 stores)
// ----------------------------------------------------------------------------
__global__ void zero_kernel(float4* __restrict__ p, int n4) {
    int i = blockIdx.x * blockDim.x + threadIdx.x;
    int stride = gridDim.x * blockDim.x;
    float4 z = make_float4(0.f, 0.f, 0.f, 0.f);
    for (; i < n4; i += stride) p[i] = z;
}

// ----------------------------------------------------------------------------
// deg / cnt accumulation over edges
// ----------------------------------------------------------------------------
__global__ void deg_cnt_kernel(const int* __restrict__ col,
                               const float* __restrict__ ew,
                               float* __restrict__ deg,
                               float* __restrict__ cnt, int E) {
    int e = blockIdx.x * blockDim.x + threadIdx.x;
    if (e >= E) return;
    int c = col[e];
    atomicAdd(&deg[c], ew[e]);
    atomicAdd(&cnt[c], 1.0f);
}

__global__ void dinv_kernel(const float* __restrict__ deg,
                            const float* __restrict__ cnt,
                            float* __restrict__ dinv,
                            float* __restrict__ icnt, int n) {
    int i = blockIdx.x * blockDim.x + threadIdx.x;
    if (i >= n) return;
    float d = deg[i];
    dinv[i] = (d > 0.f) ? rsqrtf(d) : 0.f;
    icnt[i] = 1.0f / fmaxf(cnt[i], 1.0f);
}

// ----------------------------------------------------------------------------
// Edge scatter kernels: one warp per edge, 4 floats per lane (128 per row),
// packed v4 f32 global reductions (sm_90+).
// ----------------------------------------------------------------------------
__device__ __forceinline__ void red_add_v4(float* dst, float4 v) {
    asm volatile("red.global.add.v4.f32 [%0], {%1,%2,%3,%4};"
                 :: "l"(dst), "f"(v.x), "f"(v.y), "f"(v.z), "f"(v.w)
                 : "memory");
}

__global__ void scatter_arma_kernel(const int* __restrict__ row,
                                    const int* __restrict__ col,
                                    const float* __restrict__ ew,
                                    const float* __restrict__ dinv,
                                    const float* __restrict__ src,
                                    float* __restrict__ dst, int E) {
    int lane = threadIdx.x & 31;
    int warp = (blockIdx.x * blockDim.x + threadIdx.x) >> 5;
    int nwarp = (gridDim.x * blockDim.x) >> 5;
    for (int e = warp; e < E; e += nwarp) {
        int r = __ldg(row + e);
        int c = __ldg(col + e);
        float nrm = __ldg(dinv + r) * __ldg(ew + e) * __ldg(dinv + c);
        float4 v = __ldg((const float4*)(src + (size_t)r * 128) + lane);
        v.x *= nrm; v.y *= nrm; v.z *= nrm; v.w *= nrm;
        red_add_v4(dst + (size_t)c * 128 + lane * 4, v);
    }
}

__global__ void scatter_sage_kernel(const int* __restrict__ row,
                                    const int* __restrict__ col,
                                    const float* __restrict__ ew,
                                    const float* __restrict__ src,
                                    float* __restrict__ dst, int E) {
    int lane = threadIdx.x & 31;
    int warp = (blockIdx.x * blockDim.x + threadIdx.x) >> 5;
    int nwarp = (gridDim.x * blockDim.x) >> 5;
    for (int e = warp; e < E; e += nwarp) {
        int r = __ldg(row + e);
        int c = __ldg(col + e);
        float w = __ldg(ew + e);
        float4 v = __ldg((const float4*)(src + (size_t)r * 128) + lane);
        v.x *= w; v.y *= w; v.z *= w; v.w *= w;
        red_add_v4(dst + (size_t)c * 128 + lane * 4, v);
    }
}

// ----------------------------------------------------------------------------
// SGEMM: C[M x Nw] = (rscale? diag(rs):I) * A[M x K] @ W[K x Nw] (+ bias)
// BM=128, BN=128, BK=8, 256 threads, 8x8 per thread.
// FINAL variant fuses the cell epilogue:
//   h2 = acc + r;  z = leaky(h2);  h2out = z>0 ? z : expm1(0.01*z)   [elu(leaky)]
//   h1out = relu(agg + u)                                            [elu/leaky are identity on relu output]
//   hOut[m][0:128] = h1out ; hOut[m][128:256] = h2out
// ----------------------------------------------------------------------------
template<bool HAS_BIAS, bool HAS_RSCALE, bool FINAL>
__global__ __launch_bounds__(256)
void sgemm128_kernel(const float* __restrict__ A, const float* __restrict__ W,
                     const float* __restrict__ bias, const float* __restrict__ rscale,
                     float* __restrict__ C,
                     const float* __restrict__ eAgg, const float* __restrict__ eU,
                     const float* __restrict__ eR, float* __restrict__ eOut,
                     int M, int K, int Nw) {
    __shared__ float As[8][128];
    __shared__ float Bs[8][128];

    int tid = threadIdx.x;
    int m0 = blockIdx.x * 128;
    int n0 = blockIdx.y * 128;

    int arow  = tid >> 1;         // 0..127
    int acol4 = (tid & 1) * 4;    // 0 or 4
    int brow  = tid >> 5;         // 0..7
    int bcol4 = (tid & 31) * 4;   // 0..124
    int ty = tid >> 4;            // 0..15 -> rows ty*8..ty*8+7
    int tx = tid & 15;            // 0..15 -> cols tx*8..tx*8+7

    float acc[8][8];
    #pragma unroll
    for (int i = 0; i < 8; i++)
        #pragma unroll
        for (int j = 0; j < 8; j++) acc[i][j] = 0.f;

    int gm = m0 + arow;
    float rs = 1.0f;
    if (HAS_RSCALE && gm < M) rs = __ldg(rscale + gm);
    const float* Aptr = A + (size_t)gm * K + acol4;

    for (int k0 = 0; k0 < K; k0 += 8) {
        float4 av = make_float4(0.f, 0.f, 0.f, 0.f);
        if (gm < M) av = *(const float4*)(Aptr + k0);
        if (HAS_RSCALE) { av.x *= rs; av.y *= rs; av.z *= rs; av.w *= rs; }
        As[acol4 + 0][arow] = av.x;
        As[acol4 + 1][arow] = av.y;
        As[acol4 + 2][arow] = av.z;
        As[acol4 + 3][arow] = av.w;

        float4 bv = *(const float4*)(W + (size_t)(k0 + brow) * Nw + n0 + bcol4);
        *(float4*)&Bs[brow][bcol4] = bv;
        __syncthreads();

        #pragma unroll
        for (int kk = 0; kk < 8; ++kk) {
            float a[8], b[8];
            #pragma unroll
            for (int i = 0; i < 8; i++) a[i] = As[kk][ty * 8 + i];
            #pragma unroll
            for (int j = 0; j < 8; j++) b[j] = Bs[kk][tx * 8 + j];
            #pragma unroll
            for (int i = 0; i < 8; i++)
                #pragma unroll
                for (int j = 0; j < 8; j++) acc[i][j] += a[i] * b[j];
        }
        __syncthreads();
    }

    if (!FINAL) {
        float bvals[8];
        #pragma unroll
        for (int j = 0; j < 8; j++)
            bvals[j] = HAS_BIAS ? __ldg(bias + n0 + tx * 8 + j) : 0.f;
        #pragma unroll
        for (int i = 0; i < 8; i++) {
            int m = m0 + ty * 8 + i;
            if (m >= M) continue;
            float* cp = C + (size_t)m * Nw + n0 + tx * 8;
            float4 v0 = make_float4(acc[i][0] + bvals[0], acc[i][1] + bvals[1],
                                    acc[i][2] + bvals[2], acc[i][3] + bvals[3]);
            float4 v1 = make_float4(acc[i][4] + bvals[4], acc[i][5] + bvals[5],
                                    acc[i][6] + bvals[6], acc[i][7] + bvals[7]);
            *(float4*)cp = v0;
            *(float4*)(cp + 4) = v1;
        }
    } else {
        // Nw == 128, gridDim.y == 1, n0 == 0
        #pragma unroll
        for (int i = 0; i < 8; i++) {
            int m = m0 + ty * 8 + i;
            if (m >= M) continue;
            size_t base = (size_t)m * 128 + tx * 8;
            float h1o[8], h2o[8];
            #pragma unroll
            for (int j = 0; j < 8; j++) {
                float v = acc[i][j] + __ldg(eR + base + j);     // sage_bl folded into r
                h2o[j] = (v > 0.f) ? v : expm1f(0.01f * v);     // elu(leaky(v))
                float a = __ldg(eAgg + base + j) + __ldg(eU + base + j);  // arma_b folded into u
                h1o[j] = fmaxf(a, 0.f);                         // elu(leaky(relu(x))) == relu(x)
            }
            float* op = eOut + (size_t)m * 256 + tx * 8;
            *(float4*)op        = make_float4(h1o[0], h1o[1], h1o[2], h1o[3]);
            *(float4*)(op + 4)  = make_float4(h1o[4], h1o[5], h1o[6], h1o[7]);
            *(float4*)(op + 128) = make_float4(h2o[0], h2o[1], h2o[2], h2o[3]);
            *(float4*)(op + 132) = make_float4(h2o[4], h2o[5], h2o[6], h2o[7]);
        }
    }
}

// ----------------------------------------------------------------------------
// Classifier: logits = h @ cls_w + cls_b ; out = log_softmax(logits)
// One warp per node; cls_w in smem with stride-17 padding (conflict-free).
// ----------------------------------------------------------------------------
__global__ __launch_bounds__(256)
void cls_kernel(const float* __restrict__ h, const float* __restrict__ W,
                const float* __restrict__ b, float* __restrict__ out, int M) {
    __shared__ float Ws[256 * 17];
    __shared__ float Bsm[16];
    int tid = threadIdx.x;
    for (int idx = tid; idx < 256 * 16; idx += 256) {
        int k = idx >> 4, c = idx & 15;
        Ws[k * 17 + c] = W[idx];
    }
    if (tid < 16) Bsm[tid] = b[tid];
    __syncthreads();

    int warp = tid >> 5;
    int lane = tid & 31;
    for (int n = blockIdx.x * 8 + warp; n < M; n += gridDim.x * 8) {
        float acc[16];
        #pragma unroll
        for (int c = 0; c < 16; c++) acc[c] = 0.f;
        const float* hp = h + (size_t)n * 256;
        #pragma unroll
        for (int it = 0; it < 8; it++) {
            int k = lane + it * 32;
            float hv = hp[k];
            const float* wk = &Ws[k * 17];
            #pragma unroll
            for (int c = 0; c < 16; c++) acc[c] += hv * wk[c];
        }
        #pragma unroll
        for (int c = 0; c < 16; c++) {
            #pragma unroll
            for (int off = 16; off > 0; off >>= 1)
                acc[c] += __shfl_xor_sync(0xFFFFFFFFu, acc[c], off);
        }
        float l[16];
        float mx = -3.402823e38f;
        #pragma unroll
        for (int c = 0; c < 16; c++) { l[c] = acc[c] + Bsm[c]; mx = fmaxf(mx, l[c]); }
        float se = 0.f;
        #pragma unroll
        for (int c = 0; c < 16; c++) se += expf(l[c] - mx);
        float lse = mx + logf(se);
        if (lane < 16) out[(size_t)n * 16 + lane] = l[lane] - lse;
    }
}

// ----------------------------------------------------------------------------
// Launch
// ----------------------------------------------------------------------------
static void* sym(const void* s) {
    void* p = nullptr;
    cudaGetSymbolAddress(&p, s);
    return p;
}

extern "C" void kernel_launch(void* const* d_in, const int* in_sizes, int n_in,
                              void* d_out, int out_size) {
    const float* x        = (const float*)d_in[0];
    const int*   ei       = (const int*)  d_in[1];
    const float* ew       = (const float*)d_in[2];
    const float* pre_w0   = (const float*)d_in[3];
    const float* pre_b0   = (const float*)d_in[4];
    const float* arma_w0  = (const float*)d_in[5];
    const float* arma_v0  = (const float*)d_in[6];
    const float* arma_b0  = (const float*)d_in[7];
    const float* sage_wl0 = (const float*)d_in[8];
    const float* sage_bl0 = (const float*)d_in[9];
    const float* sage_wr0 = (const float*)d_in[10];
    const float* pre_w1   = (const float*)d_in[11];
    const float* pre_b1   = (const float*)d_in[12];
    const float* arma_w1  = (const float*)d_in[13];
    const float* arma_v1  = (const float*)d_in[14];
    const float* arma_b1  = (const float*)d_in[15];
    const float* sage_wl1 = (const float*)d_in[16];
    const float* sage_bl1 = (const float*)d_in[17];
    const float* sage_wr1 = (const float*)d_in[18];
    const float* cls_w    = (const float*)d_in[19];
    const float* cls_b    = (const float*)d_in[20];
    float* out = (float*)d_out;

    const int* row = ei;
    const int* col = ei + EE;

    float* ph    = (float*)sym(g_h);
    float* phpre = (float*)sym(g_hpre);
    float* pt    = (float*)sym(g_t);
    float* pu    = (float*)sym(g_u);
    float* pr    = (float*)sym(g_r);
    float* pagg  = (float*)sym(g_agg);
    float* ps    = (float*)sym(g_s);
    float* pdeg  = (float*)sym(g_deg);
    float* pcnt  = (float*)sym(g_cnt);
    float* pdinv = (float*)sym(g_dinv);
    float* picnt = (float*)sym(g_icnt);

    const int M = NN;
    dim3 gemm_block(256);
    dim3 gemm_grid1((M + 127) / 128, 1);

    // --- degree / count / norms ---
    zero_kernel<<<(NN / 4 + 255) / 256, 256>>>((float4*)pdeg, NN / 4);
    zero_kernel<<<(NN / 4 + 255) / 256, 256>>>((float4*)pcnt, NN / 4);
    deg_cnt_kernel<<<(EE + 255) / 256, 256>>>(col, ew, pdeg, pcnt, EE);
    dinv_kernel<<<(NN + 255) / 256, 256>>>(pdeg, pcnt, pdinv, picnt, NN);

    const int n4_feat = NN * 128 / 4;
    const int zb = (n4_feat + 255) / 256;
    const int scat_blocks = (EE * 32 + 255) / 256;

    const float* cell_in = x;
    int cell_K = 128;

    const float* PW[2]  = {pre_w0, pre_w1};
    const float* PB[2]  = {pre_b0, pre_b1};
    const float* AW[2]  = {arma_w0, arma_w1};
    const float* AV[2]  = {arma_v0, arma_v1};
    const float* AB[2]  = {arma_b0, arma_b1};
    const float* SWL[2] = {sage_wl0, sage_wl1};
    const float* SBL[2] = {sage_bl0, sage_bl1};
    const float* SWR[2] = {sage_wr0, sage_wr1};

    for (int c = 0; c < 2; c++) {
        // pre-linear: h_pre = cell_in @ pre_w + pre_b
        sgemm128_kernel<true, false, false><<<gemm_grid1, gemm_block>>>(
            cell_in, PW[c], PB[c], nullptr, phpre,
            nullptr, nullptr, nullptr, nullptr, M, cell_K, 128);
        // t = h_pre @ arma_w
        sgemm128_kernel<false, false, false><<<gemm_grid1, gemm_block>>>(
            phpre, AW[c], nullptr, nullptr, pt,
            nullptr, nullptr, nullptr, nullptr, M, 128, 128);
        // u = h_pre @ arma_v + arma_b
        sgemm128_kernel<true, false, false><<<gemm_grid1, gemm_block>>>(
            phpre, AV[c], AB[c], nullptr, pu,
            nullptr, nullptr, nullptr, nullptr, M, 128, 128);
        // r = h_pre @ sage_wr + sage_bl
        sgemm128_kernel<true, false, false><<<gemm_grid1, gemm_block>>>(
            phpre, SWR[c], SBL[c], nullptr, pr,
            nullptr, nullptr, nullptr, nullptr, M, 128, 128);

        // scatters
        zero_kernel<<<zb, 256>>>((float4*)pagg, n4_feat);
        zero_kernel<<<zb, 256>>>((float4*)ps, n4_feat);
        scatter_arma_kernel<<<scat_blocks, 256>>>(row, col, ew, pdinv, pt, pagg, EE);
        scatter_sage_kernel<<<scat_blocks, 256>>>(row, col, ew, phpre, ps, EE);

        // fused: h2pre = (s * icnt) @ sage_wl ; epilogue builds h (concat, activations)
        sgemm128_kernel<false, true, true><<<gemm_grid1, gemm_block>>>(
            ps, SWL[c], nullptr, picnt, nullptr,
            pagg, pu, pr, ph, M, 128, 128);

        cell_in = ph;
        cell_K = 256;
    }

    // classifier + log_softmax
    cls_kernel<<<(M + 7) / 8, 256>>>(ph, cls_w, cls_b, out, M);
}

// round 3
// speedup vs baseline: 1.3634x; 1.3634x over previous
#include <cuda_runtime.h>
#include <math.h>
#include <stdint.h>

// Problem constants (fixed by the reference setup)
#define NN 100000
#define EE 1600000

// ----------------------------------------------------------------------------
// Scratch (device globals; allocation inside kernel_launch is forbidden)
// ----------------------------------------------------------------------------
__device__ float g_h   [(size_t)NN * 256];
__device__ float g_hpre[(size_t)NN * 128];
__device__ float g_t   [(size_t)NN * 128];
__device__ float g_u   [(size_t)NN * 128];
__device__ float g_r   [(size_t)NN * 128];
__device__ float g_agg [(size_t)NN * 128];
__device__ float g_s   [(size_t)NN * 128];
__device__ float g_deg [NN];
__device__ float g_cnt [NN];
__device__ float g_dinv[NN];
__device__ float g_icnt[NN];

// ----------------------------------------------------------------------------
// Utility: zero a float buffer
// ----------------------------------------------------------------------------
__global__ void zero_kernel(float4* __restrict__ p, size_t n4) {
    size_t i = (size_t)blockIdx.x * blockDim.x + threadIdx.x;
    size_t stride = (size_t)gridDim.x * blockDim.x;
    float4 z = make_float4(0.f, 0.f, 0.f, 0.f);
    for (; i < n4; i += stride) p[i] = z;
}

// ----------------------------------------------------------------------------
// deg / cnt accumulation over edges
// ----------------------------------------------------------------------------
__global__ void deg_cnt_kernel(const int* __restrict__ col,
                               const float* __restrict__ ew,
                               float* __restrict__ deg,
                               float* __restrict__ cnt, int E) {
    int e = blockIdx.x * blockDim.x + threadIdx.x;
    if (e >= E) return;
    int c = col[e];
    atomicAdd(&deg[c], ew[e]);
    atomicAdd(&cnt[c], 1.0f);
}

__global__ void dinv_kernel(const float* __restrict__ deg,
                            const float* __restrict__ cnt,
                            float* __restrict__ dinv,
                            float* __restrict__ icnt, int n) {
    int i = blockIdx.x * blockDim.x + threadIdx.x;
    if (i >= n) return;
    float d = deg[i];
    dinv[i] = (d > 0.f) ? rsqrtf(d) : 0.f;
    icnt[i] = 1.0f / fmaxf(cnt[i], 1.0f);
}

// ----------------------------------------------------------------------------
// Edge scatter kernels (warp per edge, packed v4 f32 global reductions)
// ----------------------------------------------------------------------------
__device__ __forceinline__ void red_add_v4(float* dst, float4 v) {
    asm volatile("red.global.add.v4.f32 [%0], {%1,%2,%3,%4};"
                 :: "l"(dst), "f"(v.x), "f"(v.y), "f"(v.z), "f"(v.w)
                 : "memory");
}

__global__ void scatter_arma_kernel(const int* __restrict__ row,
                                    const int* __restrict__ col,
                                    const float* __restrict__ ew,
                                    const float* __restrict__ dinv,
                                    const float* __restrict__ src,
                                    float* __restrict__ dst, int E) {
    int lane = threadIdx.x & 31;
    int warp = (blockIdx.x * blockDim.x + threadIdx.x) >> 5;
    int nwarp = (gridDim.x * blockDim.x) >> 5;
    for (int e = warp; e < E; e += nwarp) {
        int r = __ldg(row + e);
        int c = __ldg(col + e);
        float nrm = __ldg(dinv + r) * __ldg(ew + e) * __ldg(dinv + c);
        float4 v = __ldg((const float4*)(src + (size_t)r * 128) + lane);
        v.x *= nrm; v.y *= nrm; v.z *= nrm; v.w *= nrm;
        red_add_v4(dst + (size_t)c * 128 + lane * 4, v);
    }
}

__global__ void scatter_sage_kernel(const int* __restrict__ row,
                                    const int* __restrict__ col,
                                    const float* __restrict__ ew,
                                    const float* __restrict__ src,
                                    float* __restrict__ dst, int E) {
    int lane = threadIdx.x & 31;
    int warp = (blockIdx.x * blockDim.x + threadIdx.x) >> 5;
    int nwarp = (gridDim.x * blockDim.x) >> 5;
    for (int e = warp; e < E; e += nwarp) {
        int r = __ldg(row + e);
        int c = __ldg(col + e);
        float w = __ldg(ew + e);
        float4 v = __ldg((const float4*)(src + (size_t)r * 128) + lane);
        v.x *= w; v.y *= w; v.z *= w; v.w *= w;
        red_add_v4(dst + (size_t)c * 128 + lane * 4, v);
    }
}

// ----------------------------------------------------------------------------
// TF32 mma.sync GEMM: C[M x 128] = A[M x K] @ W[K x 128] (+bias)
// CTA 256 threads, tile 128x128, BK=64. A staged in smem (tf32-converted);
// B fragments loaded directly from global (W is L1/L2-resident).
// Warp layout: warp_m = wid&1 (2 x 64 rows), warp_n = wid>>1 (4 x 32 cols).
// MODE 0: plain (+bias) into C0.
// MODE 1: triple — blockIdx.y selects (W,bias,C); shared A.
// MODE 2: final — A rows scaled by rscale; fused cell epilogue:
//         h1 = relu(agg + u); h2 = elu(leaky(acc + r)); out = [h1 | h2].
// ----------------------------------------------------------------------------
#define LDA_S 68  // 64 + 4 pad: m-stride of 4 banks -> conflict-free LDS/STS

__device__ __forceinline__ uint32_t f2tf32(float f) {
    uint32_t u;
    asm("cvt.rna.tf32.f32 %0, %1;" : "=r"(u) : "f"(f));
    return u;
}

__device__ __forceinline__ void mma_tf32(float c[4], uint32_t a0, uint32_t a1,
                                         uint32_t a2, uint32_t a3,
                                         uint32_t b0, uint32_t b1) {
    asm volatile(
        "mma.sync.aligned.m16n8k8.row.col.f32.tf32.tf32.f32 "
        "{%0,%1,%2,%3}, {%4,%5,%6,%7}, {%8,%9}, {%0,%1,%2,%3};"
        : "+f"(c[0]), "+f"(c[1]), "+f"(c[2]), "+f"(c[3])
        : "r"(a0), "r"(a1), "r"(a2), "r"(a3), "r"(b0), "r"(b1));
}

template<int MODE>
__global__ __launch_bounds__(256, 2)
void mma_gemm_kernel(const float* __restrict__ A, int lda,
                     const float* __restrict__ W0, const float* __restrict__ W1,
                     const float* __restrict__ W2,
                     const float* __restrict__ bb0, const float* __restrict__ bb1,
                     const float* __restrict__ bb2,
                     float* __restrict__ C0, float* __restrict__ C1,
                     float* __restrict__ C2,
                     const float* __restrict__ rscale,
                     const float* __restrict__ eAgg, const float* __restrict__ eU,
                     const float* __restrict__ eR, float* __restrict__ eOut,
                     int M, int K) {
    __shared__ uint32_t smA[128 * LDA_S];

    int tid = threadIdx.x;
    int lane = tid & 31;
    int wid = tid >> 5;
    int warp_m = wid & 1;       // 0..1 -> 64-row halves
    int warp_n = wid >> 1;      // 0..3 -> 32-col quarters
    int m0 = blockIdx.x * 128;

    const float* W = W0;
    const float* bias = bb0;
    float* C = C0;
    if (MODE == 1) {
        if (blockIdx.y == 1) { W = W1; bias = bb1; C = C1; }
        else if (blockIdx.y == 2) { W = W2; bias = bb2; C = C2; }
    }

    float acc[4][4][4];
    #pragma unroll
    for (int mt = 0; mt < 4; mt++)
        #pragma unroll
        for (int nt = 0; nt < 4; nt++)
            #pragma unroll
            for (int q = 0; q < 4; q++) acc[mt][nt][q] = 0.f;

    int lr = lane >> 2;   // 0..7
    int lc = lane & 3;    // 0..3

    for (int k0 = 0; k0 < K; k0 += 64) {
        // ---- stage A chunk (128 x 64) into smem, tf32-rounded ----
        #pragma unroll
        for (int it = 0; it < 8; it++) {
            int idx = it * 256 + tid;   // 0..2047
            int m = idx >> 4;           // 0..127
            int kq = idx & 15;          // float4 index within 64 cols
            int gm = m0 + m;
            float4 v = make_float4(0.f, 0.f, 0.f, 0.f);
            if (gm < M) {
                v = *(const float4*)(A + (size_t)gm * lda + k0 + kq * 4);
                if (MODE == 2) {
                    float rs = __ldg(rscale + gm);
                    v.x *= rs; v.y *= rs; v.z *= rs; v.w *= rs;
                }
            }
            uint4 u;
            u.x = f2tf32(v.x); u.y = f2tf32(v.y);
            u.z = f2tf32(v.z); u.w = f2tf32(v.w);
            *(uint4*)&smA[m * LDA_S + kq * 4] = u;
        }
        __syncthreads();

        // ---- compute: 8 k8-steps ----
        #pragma unroll
        for (int s = 0; s < 8; s++) {
            int ks = s * 8;
            uint32_t af[4][4];
            #pragma unroll
            for (int mt = 0; mt < 4; mt++) {
                int base = (warp_m * 64 + mt * 16 + lr) * LDA_S + ks + lc;
                af[mt][0] = smA[base];
                af[mt][1] = smA[base + 8 * LDA_S];
                af[mt][2] = smA[base + 4];
                af[mt][3] = smA[base + 8 * LDA_S + 4];
            }
            int gk = k0 + ks + lc;
            #pragma unroll
            for (int nt = 0; nt < 4; nt++) {
                int gn = warp_n * 32 + nt * 8 + lr;
                uint32_t bf0 = f2tf32(__ldg(W + (size_t)gk * 128 + gn));
                uint32_t bf1 = f2tf32(__ldg(W + (size_t)(gk + 4) * 128 + gn));
                #pragma unroll
                for (int mt = 0; mt < 4; mt++)
                    mma_tf32(acc[mt][nt], af[mt][0], af[mt][1], af[mt][2], af[mt][3],
                             bf0, bf1);
            }
        }
        __syncthreads();
    }

    // ---- epilogue ----
    #pragma unroll
    for (int nt = 0; nt < 4; nt++) {
        int n = warp_n * 32 + nt * 8 + lc * 2;
        float2 bv = make_float2(0.f, 0.f);
        if (MODE != 2 && bias) bv = __ldg((const float2*)(bias + n));
        #pragma unroll
        for (int mt = 0; mt < 4; mt++) {
            #pragma unroll
            for (int h = 0; h < 2; h++) {   // h=0: rows +0, h=1: rows +8
                int gm = m0 + warp_m * 64 + mt * 16 + lr + h * 8;
                if (gm >= M) continue;
                float v0 = acc[mt][nt][h * 2 + 0];
                float v1 = acc[mt][nt][h * 2 + 1];
                if (MODE != 2) {
                    float2 o = make_float2(v0 + bv.x, v1 + bv.y);
                    *(float2*)(C + (size_t)gm * 128 + n) = o;
                } else {
                    size_t base = (size_t)gm * 128 + n;
                    float2 rv = __ldg((const float2*)(eR + base));
                    float2 gv = __ldg((const float2*)(eAgg + base));
                    float2 uv = __ldg((const float2*)(eU + base));
                    float a0 = v0 + rv.x, a1 = v1 + rv.y;
                    float2 h2v;
                    h2v.x = (a0 > 0.f) ? a0 : expm1f(0.01f * a0);
                    h2v.y = (a1 > 0.f) ? a1 : expm1f(0.01f * a1);
                    float2 h1v;
                    h1v.x = fmaxf(gv.x + uv.x, 0.f);
                    h1v.y = fmaxf(gv.y + uv.y, 0.f);
                    *(float2*)(eOut + (size_t)gm * 256 + n) = h1v;
                    *(float2*)(eOut + (size_t)gm * 256 + 128 + n) = h2v;
                }
            }
        }
    }
}

// ----------------------------------------------------------------------------
// Classifier: logits = h @ cls_w + cls_b ; out = log_softmax(logits)
// ----------------------------------------------------------------------------
__global__ __launch_bounds__(256)
void cls_kernel(const float* __restrict__ h, const float* __restrict__ W,
                const float* __restrict__ b, float* __restrict__ out, int M) {
    __shared__ float Ws[256 * 17];
    __shared__ float Bsm[16];
    int tid = threadIdx.x;
    for (int idx = tid; idx < 256 * 16; idx += 256) {
        int k = idx >> 4, c = idx & 15;
        Ws[k * 17 + c] = W[idx];
    }
    if (tid < 16) Bsm[tid] = b[tid];
    __syncthreads();

    int warp = tid >> 5;
    int lane = tid & 31;
    for (int n = blockIdx.x * 8 + warp; n < M; n += gridDim.x * 8) {
        float acc[16];
        #pragma unroll
        for (int c = 0; c < 16; c++) acc[c] = 0.f;
        const float* hp = h + (size_t)n * 256;
        #pragma unroll
        for (int it = 0; it < 8; it++) {
            int k = lane + it * 32;
            float hv = hp[k];
            const float* wk = &Ws[k * 17];
            #pragma unroll
            for (int c = 0; c < 16; c++) acc[c] += hv * wk[c];
        }
        #pragma unroll
        for (int c = 0; c < 16; c++) {
            #pragma unroll
            for (int off = 16; off > 0; off >>= 1)
                acc[c] += __shfl_xor_sync(0xFFFFFFFFu, acc[c], off);
        }
        float l[16];
        float mx = -3.402823e38f;
        #pragma unroll
        for (int c = 0; c < 16; c++) { l[c] = acc[c] + Bsm[c]; mx = fmaxf(mx, l[c]); }
        float se = 0.f;
        #pragma unroll
        for (int c = 0; c < 16; c++) se += expf(l[c] - mx);
        float lse = mx + logf(se);
        if (lane < 16) out[(size_t)n * 16 + lane] = l[lane] - lse;
    }
}

// ----------------------------------------------------------------------------
// Launch
// ----------------------------------------------------------------------------
static void* sym(const void* s) {
    void* p = nullptr;
    cudaGetSymbolAddress(&p, s);
    return p;
}

extern "C" void kernel_launch(void* const* d_in, const int* in_sizes, int n_in,
                              void* d_out, int out_size) {
    const float* x        = (const float*)d_in[0];
    const int*   ei       = (const int*)  d_in[1];
    const float* ew       = (const float*)d_in[2];
    const float* pre_w0   = (const float*)d_in[3];
    const float* pre_b0   = (const float*)d_in[4];
    const float* arma_w0  = (const float*)d_in[5];
    const float* arma_v0  = (const float*)d_in[6];
    const float* arma_b0  = (const float*)d_in[7];
    const float* sage_wl0 = (const float*)d_in[8];
    const float* sage_bl0 = (const float*)d_in[9];
    const float* sage_wr0 = (const float*)d_in[10];
    const float* pre_w1   = (const float*)d_in[11];
    const float* pre_b1   = (const float*)d_in[12];
    const float* arma_w1  = (const float*)d_in[13];
    const float* arma_v1  = (const float*)d_in[14];
    const float* arma_b1  = (const float*)d_in[15];
    const float* sage_wl1 = (const float*)d_in[16];
    const float* sage_bl1 = (const float*)d_in[17];
    const float* sage_wr1 = (const float*)d_in[18];
    const float* cls_w    = (const float*)d_in[19];
    const float* cls_b    = (const float*)d_in[20];
    float* out = (float*)d_out;

    const int* row = ei;
    const int* col = ei + EE;

    float* ph    = (float*)sym(g_h);
    float* phpre = (float*)sym(g_hpre);
    float* pt    = (float*)sym(g_t);
    float* pu    = (float*)sym(g_u);
    float* pr    = (float*)sym(g_r);
    float* pagg  = (float*)sym(g_agg);
    float* ps    = (float*)sym(g_s);
    float* pdeg  = (float*)sym(g_deg);
    float* pcnt  = (float*)sym(g_cnt);
    float* pdinv = (float*)sym(g_dinv);
    float* picnt = (float*)sym(g_icnt);

    const int M = NN;
    const int MB = (M + 127) / 128;

    // --- degree / count / norms ---
    zero_kernel<<<(NN / 4 + 255) / 256, 256>>>((float4*)pdeg, NN / 4);
    zero_kernel<<<(NN / 4 + 255) / 256, 256>>>((float4*)pcnt, NN / 4);
    deg_cnt_kernel<<<(EE + 255) / 256, 256>>>(col, ew, pdeg, pcnt, EE);
    dinv_kernel<<<(NN + 255) / 256, 256>>>(pdeg, pcnt, pdinv, picnt, NN);

    const size_t n4_feat = (size_t)NN * 128 / 4;
    const int zb = (int)((n4_feat + 255) / 256);
    const int scat_blocks = (EE * 32 + 255) / 256;

    const float* cell_in = x;
    int cell_K = 128;

    const float* PW[2]  = {pre_w0, pre_w1};
    const float* PB[2]  = {pre_b0, pre_b1};
    const float* AW[2]  = {arma_w0, arma_w1};
    const float* AV[2]  = {arma_v0, arma_v1};
    const float* AB[2]  = {arma_b0, arma_b1};
    const float* SWL[2] = {sage_wl0, sage_wl1};
    const float* SBL[2] = {sage_bl0, sage_bl1};
    const float* SWR[2] = {sage_wr0, sage_wr1};

    for (int c = 0; c < 2; c++) {
        // pre-linear: h_pre = cell_in @ pre_w + pre_b
        mma_gemm_kernel<0><<<dim3(MB, 1), 256>>>(
            cell_in, cell_K, PW[c], nullptr, nullptr, PB[c], nullptr, nullptr,
            phpre, nullptr, nullptr, nullptr,
            nullptr, nullptr, nullptr, nullptr, M, cell_K);

        // triple: t = hpre@arma_w ; u = hpre@arma_v + arma_b ; r = hpre@sage_wr + sage_bl
        mma_gemm_kernel<1><<<dim3(MB, 3), 256>>>(
            phpre, 128, AW[c], AV[c], SWR[c], nullptr, AB[c], SBL[c],
            pt, pu, pr, nullptr,
            nullptr, nullptr, nullptr, nullptr, M, 128);

        // scatters
        zero_kernel<<<zb, 256>>>((float4*)pagg, n4_feat);
        zero_kernel<<<zb, 256>>>((float4*)ps, n4_feat);
        scatter_arma_kernel<<<scat_blocks, 256>>>(row, col, ew, pdinv, pt, pagg, EE);
        scatter_sage_kernel<<<scat_blocks, 256>>>(row, col, ew, phpre, ps, EE);

        // final fused: h2pre = (s*icnt)@sage_wl ; epilogue builds h = [relu(agg+u) | elu(leaky(.+r))]
        mma_gemm_kernel<2><<<dim3(MB, 1), 256>>>(
            ps, 128, SWL[c], nullptr, nullptr, nullptr, nullptr, nullptr,
            nullptr, nullptr, nullptr, picnt,
            pagg, pu, pr, ph, M, 128);

        cell_in = ph;
        cell_K = 256;
    }

    // classifier + log_softmax
    cls_kernel<<<(M + 7) / 8, 256>>>(ph, cls_w, cls_b, out, M);
}

// round 4
// speedup vs baseline: 2.5167x; 1.8459x over previous
#include <cuda_runtime.h>
#include <math.h>
#include <stdint.h>

// Problem constants (fixed by the reference setup)
#define NN 100000
#define EE 1600000
#define SCAN_B 1024
#define NBLK ((NN + SCAN_B - 1) / SCAN_B)   // 98

// ----------------------------------------------------------------------------
// Scratch (device globals; allocation inside kernel_launch is forbidden)
// ----------------------------------------------------------------------------
__device__ float g_h    [(size_t)NN * 256];
__device__ float g_hpre [(size_t)NN * 128];
__device__ float g_aggp [(size_t)NN * 128];   // A_hat-weighted sum of hpre
__device__ float g_ss   [(size_t)NN * 128];   // SAGE mean of hpre
__device__ float g_u    [(size_t)NN * 128];
__device__ float g_r    [(size_t)NN * 128];
__device__ float  g_deg [NN];
__device__ int    g_cnti[NN];
__device__ int    g_cur [NN];
__device__ int    g_off [NN + 1];
__device__ int    g_blksum[SCAN_B];
__device__ float  g_dinv[NN];
__device__ float  g_icnt[NN];
__device__ int    g_ssrc[EE];
__device__ float2 g_scoef[EE];

// ----------------------------------------------------------------------------
// CSR build
// ----------------------------------------------------------------------------
__global__ void init_counts_kernel(float* __restrict__ deg, int* __restrict__ cnt,
                                   int* __restrict__ cur, int n) {
    int i = blockIdx.x * blockDim.x + threadIdx.x;
    if (i < n) { deg[i] = 0.f; cnt[i] = 0; cur[i] = 0; }
}

__global__ void hist_kernel(const int* __restrict__ col,
                            const float* __restrict__ ew,
                            float* __restrict__ deg, int* __restrict__ cnt, int E) {
    int e = blockIdx.x * blockDim.x + threadIdx.x;
    if (e >= E) return;
    int c = col[e];
    atomicAdd(&deg[c], ew[e]);
    atomicAdd(&cnt[c], 1);
}

__global__ void dinv_kernel(const float* __restrict__ deg,
                            const int* __restrict__ cnt,
                            float* __restrict__ dinv,
                            float* __restrict__ icnt, int n) {
    int i = blockIdx.x * blockDim.x + threadIdx.x;
    if (i >= n) return;
    float d = deg[i];
    dinv[i] = (d > 0.f) ? rsqrtf(d) : 0.f;
    icnt[i] = 1.0f / fmaxf((float)cnt[i], 1.0f);
}

// scan pass 1: per-block exclusive scan of cnt -> off, block total -> blksum
__global__ void scan1_kernel(const int* __restrict__ cnt, int* __restrict__ off,
                             int* __restrict__ blksum, int n) {
    __shared__ int sh[SCAN_B];
    int t = threadIdx.x;
    int i = blockIdx.x * SCAN_B + t;
    int v = (i < n) ? cnt[i] : 0;
    sh[t] = v;
    __syncthreads();
    for (int o = 1; o < SCAN_B; o <<= 1) {
        int x = (t >= o) ? sh[t - o] : 0;
        __syncthreads();
        sh[t] += x;
        __syncthreads();
    }
    if (i < n) off[i] = sh[t] - v;          // exclusive
    if (t == SCAN_B - 1) blksum[blockIdx.x] = sh[t];
}

// scan pass 2: single block scans blksum in-place (exclusive)
__global__ void scan2_kernel(int* __restrict__ blksum, int nb) {
    __shared__ int sh[SCAN_B];
    int t = threadIdx.x;
    int v = (t < nb) ? blksum[t] : 0;
    sh[t] = v;
    __syncthreads();
    for (int o = 1; o < SCAN_B; o <<= 1) {
        int x = (t >= o) ? sh[t - o] : 0;
        __syncthreads();
        sh[t] += x;
        __syncthreads();
    }
    if (t < nb) blksum[t] = sh[t] - v;
}

// scan pass 3: add block offsets; set off[n] = E
__global__ void scan3_kernel(int* __restrict__ off, const int* __restrict__ blksum,
                             int n, int E) {
    int i = blockIdx.x * blockDim.x + threadIdx.x;
    if (i < n) off[i] += blksum[i / SCAN_B];
    if (i == 0) off[n] = E;
}

// scatter edges into CSR order; precompute both coefficients
__global__ void edge_sort_kernel(const int* __restrict__ row,
                                 const int* __restrict__ col,
                                 const float* __restrict__ ew,
                                 const int* __restrict__ off,
                                 int* __restrict__ cur,
                                 const float* __restrict__ dinv,
                                 const float* __restrict__ icnt,
                                 int* __restrict__ ssrc,
                                 float2* __restrict__ scoef, int E) {
    int e = blockIdx.x * blockDim.x + threadIdx.x;
    if (e >= E) return;
    int c = col[e];
    int r = row[e];
    float w = ew[e];
    int p = off[c] + atomicAdd(&cur[c], 1);
    ssrc[p] = r;
    scoef[p] = make_float2(dinv[r] * w * dinv[c], w * icnt[c]);
}

// ----------------------------------------------------------------------------
// Atomic-free dual aggregation: warp per destination node.
//   aggp[n] = sum_e norm_e * hpre[src_e]
//   ss[n]   = sum_e (ew_e*icnt_n) * hpre[src_e]
// ----------------------------------------------------------------------------
__global__ __launch_bounds__(256)
void aggregate_kernel(const int* __restrict__ off,
                      const int* __restrict__ ssrc,
                      const float2* __restrict__ scoef,
                      const float* __restrict__ hpre,
                      float* __restrict__ aggp,
                      float* __restrict__ ss, int N) {
    int lane = threadIdx.x & 31;
    int w = (blockIdx.x * blockDim.x + threadIdx.x) >> 5;
    if (w >= N) return;
    int s0 = __ldg(off + w);
    int s1 = __ldg(off + w + 1);
    float4 a1 = make_float4(0.f, 0.f, 0.f, 0.f);
    float4 a2 = make_float4(0.f, 0.f, 0.f, 0.f);
    #pragma unroll 2
    for (int e = s0; e < s1; e++) {
        int sr = __ldg(ssrc + e);
        float2 c = __ldg(scoef + e);
        float4 v = __ldg((const float4*)(hpre + (size_t)sr * 128) + lane);
        a1.x += c.x * v.x; a1.y += c.x * v.y; a1.z += c.x * v.z; a1.w += c.x * v.w;
        a2.x += c.y * v.x; a2.y += c.y * v.y; a2.z += c.y * v.z; a2.w += c.y * v.w;
    }
    ((float4*)(aggp + (size_t)w * 128))[lane] = a1;
    ((float4*)(ss   + (size_t)w * 128))[lane] = a2;
}

// ----------------------------------------------------------------------------
// TF32 mma.sync GEMM: C[M x 128] = A[M x K] @ W[K x 128] (+bias)
// CTA 256 threads, tile 128x128, BK=64. A staged in smem (tf32-converted);
// B fragments loaded directly from global (W is L1/L2-resident).
// MODE 0: single plain + bias into C0.
// MODE 1: dual  — blockIdx.y picks (W,bias,C) in {0,1}; shared A.
// MODE 3: dual final — blockIdx.y picks (A,W,addend); epilogue:
//         y=0: out[:,0:128]   = relu(acc + u)
//         y=1: out[:,128:256] = elu(leaky(acc + r))
// ----------------------------------------------------------------------------
#define LDA_S 68  // 64 + 4 pad

__device__ __forceinline__ uint32_t f2tf32(float f) {
    uint32_t u;
    asm("cvt.rna.tf32.f32 %0, %1;" : "=r"(u) : "f"(f));
    return u;
}

__device__ __forceinline__ void mma_tf32(float c[4], uint32_t a0, uint32_t a1,
                                         uint32_t a2, uint32_t a3,
                                         uint32_t b0, uint32_t b1) {
    asm volatile(
        "mma.sync.aligned.m16n8k8.row.col.f32.tf32.tf32.f32 "
        "{%0,%1,%2,%3}, {%4,%5,%6,%7}, {%8,%9}, {%0,%1,%2,%3};"
        : "+f"(c[0]), "+f"(c[1]), "+f"(c[2]), "+f"(c[3])
        : "r"(a0), "r"(a1), "r"(a2), "r"(a3), "r"(b0), "r"(b1));
}

template<int MODE>
__global__ __launch_bounds__(256, 2)
void mma_gemm_kernel(const float* __restrict__ A0, const float* __restrict__ A1,
                     int lda,
                     const float* __restrict__ W0, const float* __restrict__ W1,
                     const float* __restrict__ bb0, const float* __restrict__ bb1,
                     float* __restrict__ C0, float* __restrict__ C1,
                     const float* __restrict__ add0, const float* __restrict__ add1,
                     float* __restrict__ eOut,
                     int M, int K) {
    __shared__ uint32_t smA[128 * LDA_S];

    int tid = threadIdx.x;
    int lane = tid & 31;
    int wid = tid >> 5;
    int warp_m = wid & 1;       // 0..1 -> 64-row halves
    int warp_n = wid >> 1;      // 0..3 -> 32-col quarters
    int m0 = blockIdx.x * 128;
    int y = blockIdx.y;

    const float* A = A0;
    const float* W = W0;
    const float* bias = bb0;
    float* C = C0;
    const float* addN = add0;
    if (MODE == 1 && y == 1) { W = W1; bias = bb1; C = C1; }
    if (MODE == 3 && y == 1) { A = A1; W = W1; addN = add1; }

    float acc[4][4][4];
    #pragma unroll
    for (int mt = 0; mt < 4; mt++)
        #pragma unroll
        for (int nt = 0; nt < 4; nt++)
            #pragma unroll
            for (int q = 0; q < 4; q++) acc[mt][nt][q] = 0.f;

    int lr = lane >> 2;   // 0..7
    int lc = lane & 3;    // 0..3

    for (int k0 = 0; k0 < K; k0 += 64) {
        // ---- stage A chunk (128 x 64) into smem, tf32-rounded ----
        #pragma unroll
        for (int it = 0; it < 8; it++) {
            int idx = it * 256 + tid;   // 0..2047
            int m = idx >> 4;           // 0..127
            int kq = idx & 15;          // float4 index within 64 cols
            int gm = m0 + m;
            float4 v = make_float4(0.f, 0.f, 0.f, 0.f);
            if (gm < M)
                v = *(const float4*)(A + (size_t)gm * lda + k0 + kq * 4);
            uint4 u;
            u.x = f2tf32(v.x); u.y = f2tf32(v.y);
            u.z = f2tf32(v.z); u.w = f2tf32(v.w);
            *(uint4*)&smA[m * LDA_S + kq * 4] = u;
        }
        __syncthreads();

        // ---- compute: 8 k8-steps ----
        #pragma unroll
        for (int s = 0; s < 8; s++) {
            int ks = s * 8;
            uint32_t af[4][4];
            #pragma unroll
            for (int mt = 0; mt < 4; mt++) {
                int base = (warp_m * 64 + mt * 16 + lr) * LDA_S + ks + lc;
                af[mt][0] = smA[base];
                af[mt][1] = smA[base + 8 * LDA_S];
                af[mt][2] = smA[base + 4];
                af[mt][3] = smA[base + 8 * LDA_S + 4];
            }
            int gk = k0 + ks + lc;
            #pragma unroll
            for (int nt = 0; nt < 4; nt++) {
                int gn = warp_n * 32 + nt * 8 + lr;
                uint32_t bf0 = f2tf32(__ldg(W + (size_t)gk * 128 + gn));
                uint32_t bf1 = f2tf32(__ldg(W + (size_t)(gk + 4) * 128 + gn));
                #pragma unroll
                for (int mt = 0; mt < 4; mt++)
                    mma_tf32(acc[mt][nt], af[mt][0], af[mt][1], af[mt][2], af[mt][3],
                             bf0, bf1);
            }
        }
        __syncthreads();
    }

    // ---- epilogue ----
    #pragma unroll
    for (int nt = 0; nt < 4; nt++) {
        int n = warp_n * 32 + nt * 8 + lc * 2;
        float2 bv = make_float2(0.f, 0.f);
        if (MODE != 3 && bias) bv = __ldg((const float2*)(bias + n));
        #pragma unroll
        for (int mt = 0; mt < 4; mt++) {
            #pragma unroll
            for (int h = 0; h < 2; h++) {
                int gm = m0 + warp_m * 64 + mt * 16 + lr + h * 8;
                if (gm >= M) continue;
                float v0 = acc[mt][nt][h * 2 + 0];
                float v1 = acc[mt][nt][h * 2 + 1];
                if (MODE != 3) {
                    float2 o = make_float2(v0 + bv.x, v1 + bv.y);
                    *(float2*)(C + (size_t)gm * 128 + n) = o;
                } else {
                    float2 av = __ldg((const float2*)(addN + (size_t)gm * 128 + n));
                    float a0 = v0 + av.x, a1 = v1 + av.y;
                    float2 o;
                    if (y == 0) {               // h1 = relu
                        o.x = fmaxf(a0, 0.f);
                        o.y = fmaxf(a1, 0.f);
                    } else {                    // h2 = elu(leaky(.))
                        o.x = (a0 > 0.f) ? a0 : expm1f(0.01f * a0);
                        o.y = (a1 > 0.f) ? a1 : expm1f(0.01f * a1);
                    }
                    *(float2*)(eOut + (size_t)gm * 256 + y * 128 + n) = o;
                }
            }
        }
    }
}

// ----------------------------------------------------------------------------
// Classifier: logits = h @ cls_w + cls_b ; out = log_softmax(logits)
// ----------------------------------------------------------------------------
__global__ __launch_bounds__(256)
void cls_kernel(const float* __restrict__ h, const float* __restrict__ W,
                const float* __restrict__ b, float* __restrict__ out, int M) {
    __shared__ float Ws[256 * 17];
    __shared__ float Bsm[16];
    int tid = threadIdx.x;
    for (int idx = tid; idx < 256 * 16; idx += 256) {
        int k = idx >> 4, c = idx & 15;
        Ws[k * 17 + c] = W[idx];
    }
    if (tid < 16) Bsm[tid] = b[tid];
    __syncthreads();

    int warp = tid >> 5;
    int lane = tid & 31;
    for (int n = blockIdx.x * 8 + warp; n < M; n += gridDim.x * 8) {
        float acc[16];
        #pragma unroll
        for (int c = 0; c < 16; c++) acc[c] = 0.f;
        const float* hp = h + (size_t)n * 256;
        #pragma unroll
        for (int it = 0; it < 8; it++) {
            int k = lane + it * 32;
            float hv = hp[k];
            const float* wk = &Ws[k * 17];
            #pragma unroll
            for (int c = 0; c < 16; c++) acc[c] += hv * wk[c];
        }
        #pragma unroll
        for (int c = 0; c < 16; c++) {
            #pragma unroll
            for (int off = 16; off > 0; off >>= 1)
                acc[c] += __shfl_xor_sync(0xFFFFFFFFu, acc[c], off);
        }
        float l[16];
        float mx = -3.402823e38f;
        #pragma unroll
        for (int c = 0; c < 16; c++) { l[c] = acc[c] + Bsm[c]; mx = fmaxf(mx, l[c]); }
        float se = 0.f;
        #pragma unroll
        for (int c = 0; c < 16; c++) se += expf(l[c] - mx);
        float lse = mx + logf(se);
        if (lane < 16) out[(size_t)n * 16 + lane] = l[lane] - lse;
    }
}

// ----------------------------------------------------------------------------
// Launch
// ----------------------------------------------------------------------------
static void* sym(const void* s) {
    void* p = nullptr;
    cudaGetSymbolAddress(&p, s);
    return p;
}

extern "C" void kernel_launch(void* const* d_in, const int* in_sizes, int n_in,
                              void* d_out, int out_size) {
    const float* x        = (const float*)d_in[0];
    const int*   ei       = (const int*)  d_in[1];
    const float* ew       = (const float*)d_in[2];
    const float* pre_w0   = (const float*)d_in[3];
    const float* pre_b0   = (const float*)d_in[4];
    const float* arma_w0  = (const float*)d_in[5];
    const float* arma_v0  = (const float*)d_in[6];
    const float* arma_b0  = (const float*)d_in[7];
    const float* sage_wl0 = (const float*)d_in[8];
    const float* sage_bl0 = (const float*)d_in[9];
    const float* sage_wr0 = (const float*)d_in[10];
    const float* pre_w1   = (const float*)d_in[11];
    const float* pre_b1   = (const float*)d_in[12];
    const float* arma_w1  = (const float*)d_in[13];
    const float* arma_v1  = (const float*)d_in[14];
    const float* arma_b1  = (const float*)d_in[15];
    const float* sage_wl1 = (const float*)d_in[16];
    const float* sage_bl1 = (const float*)d_in[17];
    const float* sage_wr1 = (const float*)d_in[18];
    const float* cls_w    = (const float*)d_in[19];
    const float* cls_b    = (const float*)d_in[20];
    float* out = (float*)d_out;

    const int* row = ei;
    const int* col = ei + EE;

    float*  ph    = (float*) sym(g_h);
    float*  phpre = (float*) sym(g_hpre);
    float*  paggp = (float*) sym(g_aggp);
    float*  pss   = (float*) sym(g_ss);
    float*  pu    = (float*) sym(g_u);
    float*  pr    = (float*) sym(g_r);
    float*  pdeg  = (float*) sym(g_deg);
    int*    pcnti = (int*)   sym(g_cnti);
    int*    pcur  = (int*)   sym(g_cur);
    int*    poff  = (int*)   sym(g_off);
    int*    pblk  = (int*)   sym(g_blksum);
    float*  pdinv = (float*) sym(g_dinv);
    float*  picnt = (float*) sym(g_icnt);
    int*    pssrc = (int*)   sym(g_ssrc);
    float2* pscoef= (float2*)sym(g_scoef);

    const int M = NN;
    const int MB = (M + 127) / 128;

    // ---- CSR build (once per call; shared by both cells) ----
    init_counts_kernel<<<(NN + 255) / 256, 256>>>(pdeg, pcnti, pcur, NN);
    hist_kernel<<<(EE + 255) / 256, 256>>>(col, ew, pdeg, pcnti, EE);
    dinv_kernel<<<(NN + 255) / 256, 256>>>(pdeg, pcnti, pdinv, picnt, NN);
    scan1_kernel<<<NBLK, SCAN_B>>>(pcnti, poff, pblk, NN);
    scan2_kernel<<<1, SCAN_B>>>(pblk, NBLK);
    scan3_kernel<<<(NN + 255) / 256, 256>>>(poff, pblk, NN, EE);
    edge_sort_kernel<<<(EE + 255) / 256, 256>>>(row, col, ew, poff, pcur,
                                                pdinv, picnt, pssrc, pscoef, EE);

    const float* cell_in = x;
    int cell_K = 128;

    const float* PW[2]  = {pre_w0, pre_w1};
    const float* PB[2]  = {pre_b0, pre_b1};
    const float* AW[2]  = {arma_w0, arma_w1};
    const float* AV[2]  = {arma_v0, arma_v1};
    const float* AB[2]  = {arma_b0, arma_b1};
    const float* SWL[2] = {sage_wl0, sage_wl1};
    const float* SBL[2] = {sage_bl0, sage_bl1};
    const float* SWR[2] = {sage_wr0, sage_wr1};

    const int agg_blocks = (NN * 32 + 255) / 256;

    for (int c = 0; c < 2; c++) {
        // pre-linear: h_pre = cell_in @ pre_w + pre_b
        mma_gemm_kernel<0><<<dim3(MB, 1), 256>>>(
            cell_in, nullptr, cell_K, PW[c], nullptr, PB[c], nullptr,
            phpre, nullptr, nullptr, nullptr, nullptr, M, cell_K);

        // dual: u = hpre@arma_v + arma_b ; r = hpre@sage_wr + sage_bl
        mma_gemm_kernel<1><<<dim3(MB, 2), 256>>>(
            phpre, nullptr, 128, AV[c], SWR[c], AB[c], SBL[c],
            pu, pr, nullptr, nullptr, nullptr, M, 128);

        // atomic-free dual aggregation of hpre
        aggregate_kernel<<<agg_blocks, 256>>>(poff, pssrc, pscoef, phpre,
                                              paggp, pss, NN);

        // dual final: y=0: h[:,0:128]=relu(aggp@arma_w + u)
        //             y=1: h[:,128:256]=elu(leaky(ss@sage_wl + r))
        mma_gemm_kernel<3><<<dim3(MB, 2), 256>>>(
            paggp, pss, 128, AW[c], SWL[c], nullptr, nullptr,
            nullptr, nullptr, pu, pr, ph, M, 128);

        cell_in = ph;
        cell_K = 256;
    }

    // classifier + log_softmax
    cls_kernel<<<(M + 7) / 8, 256>>>(ph, cls_w, cls_b, out, M);
}

// round 5
// speedup vs baseline: 2.6053x; 1.0352x over previous
#include <cuda_runtime.h>
#include <cuda_bf16.h>
#include <math.h>
#include <stdint.h>

// Problem constants (fixed by the reference setup)
#define NN 100000
#define EE 1600000
#define SCAN_B 1024
#define NBLK ((NN + SCAN_B - 1) / SCAN_B)   // 98

// ----------------------------------------------------------------------------
// Scratch (device globals; allocation inside kernel_launch is forbidden)
// ----------------------------------------------------------------------------
__device__ float g_h [(size_t)NN * 256];
__device__ float g_u [(size_t)NN * 128];
__device__ float g_r [(size_t)NN * 128];
__device__ __nv_bfloat16 g_tb[(size_t)NN * 128];  // t  = hpre@arma_w   (bf16)
__device__ __nv_bfloat16 g_sb[(size_t)NN * 128];  // s2 = hpre@sage_wl  (bf16)
__device__ float  g_deg [NN];
__device__ int    g_cnti[NN];
__device__ int    g_cur [NN];
__device__ int    g_off [NN + 1];
__device__ int    g_blksum[SCAN_B];
__device__ float  g_dinv[NN];
__device__ float  g_icnt[NN];
__device__ int    g_ssrc[EE];
__device__ float2 g_scoef[EE];
// composed weights/biases (max cell_K = 256)
__device__ float g_Wt[256 * 128];
__device__ float g_Ws[256 * 128];
__device__ float g_Wu[256 * 128];
__device__ float g_Wr[256 * 128];
__device__ float g_bt[128];
__device__ float g_bs[128];
__device__ float g_bu[128];
__device__ float g_br[128];

// ----------------------------------------------------------------------------
// CSR build
// ----------------------------------------------------------------------------
__global__ void init_counts_kernel(float* __restrict__ deg, int* __restrict__ cnt,
                                   int* __restrict__ cur, int n) {
    int i = blockIdx.x * blockDim.x + threadIdx.x;
    if (i < n) { deg[i] = 0.f; cnt[i] = 0; cur[i] = 0; }
}

__global__ void hist_kernel(const int* __restrict__ col,
                            const float* __restrict__ ew,
                            float* __restrict__ deg, int* __restrict__ cnt, int E) {
    int e = blockIdx.x * blockDim.x + threadIdx.x;
    if (e >= E) return;
    int c = col[e];
    atomicAdd(&deg[c], ew[e]);
    atomicAdd(&cnt[c], 1);
}

__global__ void dinv_kernel(const float* __restrict__ deg,
                            const int* __restrict__ cnt,
                            float* __restrict__ dinv,
                            float* __restrict__ icnt, int n) {
    int i = blockIdx.x * blockDim.x + threadIdx.x;
    if (i >= n) return;
    float d = deg[i];
    dinv[i] = (d > 0.f) ? rsqrtf(d) : 0.f;
    icnt[i] = 1.0f / fmaxf((float)cnt[i], 1.0f);
}

__global__ void scan1_kernel(const int* __restrict__ cnt, int* __restrict__ off,
                             int* __restrict__ blksum, int n) {
    __shared__ int sh[SCAN_B];
    int t = threadIdx.x;
    int i = blockIdx.x * SCAN_B + t;
    int v = (i < n) ? cnt[i] : 0;
    sh[t] = v;
    __syncthreads();
    for (int o = 1; o < SCAN_B; o <<= 1) {
        int x = (t >= o) ? sh[t - o] : 0;
        __syncthreads();
        sh[t] += x;
        __syncthreads();
    }
    if (i < n) off[i] = sh[t] - v;          // exclusive
    if (t == SCAN_B - 1) blksum[blockIdx.x] = sh[t];
}

__global__ void scan2_kernel(int* __restrict__ blksum, int nb) {
    __shared__ int sh[SCAN_B];
    int t = threadIdx.x;
    int v = (t < nb) ? blksum[t] : 0;
    sh[t] = v;
    __syncthreads();
    for (int o = 1; o < SCAN_B; o <<= 1) {
        int x = (t >= o) ? sh[t - o] : 0;
        __syncthreads();
        sh[t] += x;
        __syncthreads();
    }
    if (t < nb) blksum[t] = sh[t] - v;
}

__global__ void scan3_kernel(int* __restrict__ off, const int* __restrict__ blksum,
                             int n, int E) {
    int i = blockIdx.x * blockDim.x + threadIdx.x;
    if (i < n) off[i] += blksum[i / SCAN_B];
    if (i == 0) off[n] = E;
}

__global__ void edge_sort_kernel(const int* __restrict__ row,
                                 const int* __restrict__ col,
                                 const float* __restrict__ ew,
                                 const int* __restrict__ off,
                                 int* __restrict__ cur,
                                 const float* __restrict__ dinv,
                                 const float* __restrict__ icnt,
                                 int* __restrict__ ssrc,
                                 float2* __restrict__ scoef, int E) {
    int e = blockIdx.x * blockDim.x + threadIdx.x;
    if (e >= E) return;
    int c = col[e];
    int r = row[e];
    float w = ew[e];
    int p = off[c] + atomicAdd(&cur[c], 1);
    ssrc[p] = r;
    scoef[p] = make_float2(dinv[r] * w * dinv[c], w * icnt[c]);
}

// ----------------------------------------------------------------------------
// Weight composition: Wo[y][k][n] = sum_j pre_w[k][j] * X_y[j][n]
// grid (K*128/256, 4), block 256. Tiny GEMMs (<= 33 MFLOP total).
// ----------------------------------------------------------------------------
__global__ void compose_w_kernel(const float* __restrict__ pre_w, int K,
                                 const float* __restrict__ X0,
                                 const float* __restrict__ X1,
                                 const float* __restrict__ X2,
                                 const float* __restrict__ X3,
                                 float* __restrict__ O0, float* __restrict__ O1,
                                 float* __restrict__ O2, float* __restrict__ O3) {
    int idx = blockIdx.x * blockDim.x + threadIdx.x;
    if (idx >= K * 128) return;
    int k = idx >> 7;
    int n = idx & 127;
    const float* X = X0;
    float* O = O0;
    if (blockIdx.y == 1) { X = X1; O = O1; }
    else if (blockIdx.y == 2) { X = X2; O = O2; }
    else if (blockIdx.y == 3) { X = X3; O = O3; }
    float acc = 0.f;
    const float* pw = pre_w + (size_t)k * 128;
    #pragma unroll 8
    for (int j = 0; j < 128; j++)
        acc += pw[j] * __ldg(X + (size_t)j * 128 + n);
    O[idx] = acc;
}

// bo[y][n] = sum_j pre_b[j] * X_y[j][n] + extra_y[n]
__global__ void compose_b_kernel(const float* __restrict__ pre_b,
                                 const float* __restrict__ X0,
                                 const float* __restrict__ X1,
                                 const float* __restrict__ X2,
                                 const float* __restrict__ X3,
                                 const float* __restrict__ e2,  // arma_b (for u)
                                 const float* __restrict__ e3,  // sage_bl (for r)
                                 float* __restrict__ O0, float* __restrict__ O1,
                                 float* __restrict__ O2, float* __restrict__ O3) {
    int tid = threadIdx.x;           // 512 threads: y = tid/128, n = tid%128
    int y = tid >> 7;
    int n = tid & 127;
    const float* X = (y == 0) ? X0 : (y == 1) ? X1 : (y == 2) ? X2 : X3;
    float acc = 0.f;
    #pragma unroll 8
    for (int j = 0; j < 128; j++)
        acc += pre_b[j] * __ldg(X + (size_t)j * 128 + n);
    if (y == 2) acc += e2[n];
    if (y == 3) acc += e3[n];
    float* O = (y == 0) ? O0 : (y == 1) ? O1 : (y == 2) ? O2 : O3;
    O[n] = acc;
}

// ----------------------------------------------------------------------------
// TF32 mma.sync quad GEMM from composed weights:
//   y=0: T = A@Wt + bt  (bf16 out)     y=1: S = A@Ws + bs  (bf16 out)
//   y=2: U = A@Wu + bu  (fp32 out)     y=3: R = A@Wr + br  (fp32 out)
// CTA 256 threads, tile 128x128, BK=64. A staged in smem (tf32); B from global.
// ----------------------------------------------------------------------------
#define LDA_S 68  // 64 + 4 pad

__device__ __forceinline__ uint32_t f2tf32(float f) {
    uint32_t u;
    asm("cvt.rna.tf32.f32 %0, %1;" : "=r"(u) : "f"(f));
    return u;
}

__device__ __forceinline__ void mma_tf32(float c[4], uint32_t a0, uint32_t a1,
                                         uint32_t a2, uint32_t a3,
                                         uint32_t b0, uint32_t b1) {
    asm volatile(
        "mma.sync.aligned.m16n8k8.row.col.f32.tf32.tf32.f32 "
        "{%0,%1,%2,%3}, {%4,%5,%6,%7}, {%8,%9}, {%0,%1,%2,%3};"
        : "+f"(c[0]), "+f"(c[1]), "+f"(c[2]), "+f"(c[3])
        : "r"(a0), "r"(a1), "r"(a2), "r"(a3), "r"(b0), "r"(b1));
}

__global__ __launch_bounds__(256, 2)
void quad_gemm_kernel(const float* __restrict__ A, int lda,
                      const float* __restrict__ Wt, const float* __restrict__ Ws,
                      const float* __restrict__ Wu, const float* __restrict__ Wr,
                      const float* __restrict__ bt, const float* __restrict__ bs,
                      const float* __restrict__ bu, const float* __restrict__ br,
                      __nv_bfloat16* __restrict__ T, __nv_bfloat16* __restrict__ S,
                      float* __restrict__ U, float* __restrict__ R,
                      int M, int K) {
    __shared__ uint32_t smA[128 * LDA_S];

    int tid = threadIdx.x;
    int lane = tid & 31;
    int wid = tid >> 5;
    int warp_m = wid & 1;
    int warp_n = wid >> 1;
    int m0 = blockIdx.x * 128;
    int y = blockIdx.y;

    const float* W = (y == 0) ? Wt : (y == 1) ? Ws : (y == 2) ? Wu : Wr;
    const float* bias = (y == 0) ? bt : (y == 1) ? bs : (y == 2) ? bu : br;

    float acc[4][4][4];
    #pragma unroll
    for (int mt = 0; mt < 4; mt++)
        #pragma unroll
        for (int nt = 0; nt < 4; nt++)
            #pragma unroll
            for (int q = 0; q < 4; q++) acc[mt][nt][q] = 0.f;

    int lr = lane >> 2;
    int lc = lane & 3;

    for (int k0 = 0; k0 < K; k0 += 64) {
        #pragma unroll
        for (int it = 0; it < 8; it++) {
            int idx = it * 256 + tid;
            int m = idx >> 4;
            int kq = idx & 15;
            int gm = m0 + m;
            float4 v = make_float4(0.f, 0.f, 0.f, 0.f);
            if (gm < M)
                v = *(const float4*)(A + (size_t)gm * lda + k0 + kq * 4);
            uint4 u;
            u.x = f2tf32(v.x); u.y = f2tf32(v.y);
            u.z = f2tf32(v.z); u.w = f2tf32(v.w);
            *(uint4*)&smA[m * LDA_S + kq * 4] = u;
        }
        __syncthreads();

        #pragma unroll
        for (int s = 0; s < 8; s++) {
            int ks = s * 8;
            uint32_t af[4][4];
            #pragma unroll
            for (int mt = 0; mt < 4; mt++) {
                int base = (warp_m * 64 + mt * 16 + lr) * LDA_S + ks + lc;
                af[mt][0] = smA[base];
                af[mt][1] = smA[base + 8 * LDA_S];
                af[mt][2] = smA[base + 4];
                af[mt][3] = smA[base + 8 * LDA_S + 4];
            }
            int gk = k0 + ks + lc;
            #pragma unroll
            for (int nt = 0; nt < 4; nt++) {
                int gn = warp_n * 32 + nt * 8 + lr;
                uint32_t bf0 = f2tf32(__ldg(W + (size_t)gk * 128 + gn));
                uint32_t bf1 = f2tf32(__ldg(W + (size_t)(gk + 4) * 128 + gn));
                #pragma unroll
                for (int mt = 0; mt < 4; mt++)
                    mma_tf32(acc[mt][nt], af[mt][0], af[mt][1], af[mt][2], af[mt][3],
                             bf0, bf1);
            }
        }
        __syncthreads();
    }

    // ---- epilogue ----
    #pragma unroll
    for (int nt = 0; nt < 4; nt++) {
        int n = warp_n * 32 + nt * 8 + lc * 2;
        float2 bv = __ldg((const float2*)(bias + n));
        #pragma unroll
        for (int mt = 0; mt < 4; mt++) {
            #pragma unroll
            for (int h = 0; h < 2; h++) {
                int gm = m0 + warp_m * 64 + mt * 16 + lr + h * 8;
                if (gm >= M) continue;
                float v0 = acc[mt][nt][h * 2 + 0] + bv.x;
                float v1 = acc[mt][nt][h * 2 + 1] + bv.y;
                if (y < 2) {
                    __nv_bfloat16* P = (y == 0) ? T : S;
                    __nv_bfloat162 o = __float22bfloat162_rn(make_float2(v0, v1));
                    *(__nv_bfloat162*)(P + (size_t)gm * 128 + n) = o;
                } else {
                    float* P = (y == 2) ? U : R;
                    *(float2*)(P + (size_t)gm * 128 + n) = make_float2(v0, v1);
                }
            }
        }
    }
}

// ----------------------------------------------------------------------------
// Fused aggregation + cell epilogue: warp per destination node.
//   agg1 = sum_e norm_e      * t[src_e]   (bf16 gathers, fp32 accum)
//   agg2 = sum_e (ew*icnt)_e * s2[src_e]
//   h[:,0:128]   = relu(agg1 + u)
//   h[:,128:256] = elu(leaky(agg2 + r))
// ----------------------------------------------------------------------------
__global__ __launch_bounds__(256)
void agg_epi_kernel(const int* __restrict__ off,
                    const int* __restrict__ ssrc,
                    const float2* __restrict__ scoef,
                    const __nv_bfloat16* __restrict__ T,
                    const __nv_bfloat16* __restrict__ S,
                    const float* __restrict__ U,
                    const float* __restrict__ R,
                    float* __restrict__ H, int N) {
    int lane = threadIdx.x & 31;
    int w = (blockIdx.x * blockDim.x + threadIdx.x) >> 5;
    if (w >= N) return;
    int s0 = __ldg(off + w);
    int s1 = __ldg(off + w + 1);
    float a1x = 0.f, a1y = 0.f, a1z = 0.f, a1w = 0.f;
    float a2x = 0.f, a2y = 0.f, a2z = 0.f, a2w = 0.f;
    #pragma unroll 2
    for (int e = s0; e < s1; e++) {
        int sr = __ldg(ssrc + e);
        float2 c = __ldg(scoef + e);
        uint2 tv = __ldg((const uint2*)(T + (size_t)sr * 128) + lane);
        uint2 sv = __ldg((const uint2*)(S + (size_t)sr * 128) + lane);
        float2 t0 = __bfloat1622float2(*(__nv_bfloat162*)&tv.x);
        float2 t1 = __bfloat1622float2(*(__nv_bfloat162*)&tv.y);
        float2 q0 = __bfloat1622float2(*(__nv_bfloat162*)&sv.x);
        float2 q1 = __bfloat1622float2(*(__nv_bfloat162*)&sv.y);
        a1x += c.x * t0.x; a1y += c.x * t0.y; a1z += c.x * t1.x; a1w += c.x * t1.y;
        a2x += c.y * q0.x; a2y += c.y * q0.y; a2z += c.y * q1.x; a2w += c.y * q1.y;
    }
    size_t base = (size_t)w * 128 + lane * 4;
    float4 uv = __ldg((const float4*)(U + base));
    float4 rv = __ldg((const float4*)(R + base));
    float4 h1, h2;
    h1.x = fmaxf(a1x + uv.x, 0.f);
    h1.y = fmaxf(a1y + uv.y, 0.f);
    h1.z = fmaxf(a1z + uv.z, 0.f);
    h1.w = fmaxf(a1w + uv.w, 0.f);
    float v;
    v = a2x + rv.x; h2.x = (v > 0.f) ? v : expm1f(0.01f * v);
    v = a2y + rv.y; h2.y = (v > 0.f) ? v : expm1f(0.01f * v);
    v = a2z + rv.z; h2.z = (v > 0.f) ? v : expm1f(0.01f * v);
    v = a2w + rv.w; h2.w = (v > 0.f) ? v : expm1f(0.01f * v);
    *(float4*)(H + (size_t)w * 256 + lane * 4) = h1;
    *(float4*)(H + (size_t)w * 256 + 128 + lane * 4) = h2;
}

// ----------------------------------------------------------------------------
// Classifier: logits = h @ cls_w + cls_b ; out = log_softmax(logits)
// ----------------------------------------------------------------------------
__global__ __launch_bounds__(256)
void cls_kernel(const float* __restrict__ h, const float* __restrict__ W,
                const float* __restrict__ b, float* __restrict__ out, int M) {
    __shared__ float Ws[256 * 17];
    __shared__ float Bsm[16];
    int tid = threadIdx.x;
    for (int idx = tid; idx < 256 * 16; idx += 256) {
        int k = idx >> 4, c = idx & 15;
        Ws[k * 17 + c] = W[idx];
    }
    if (tid < 16) Bsm[tid] = b[tid];
    __syncthreads();

    int warp = tid >> 5;
    int lane = tid & 31;
    for (int n = blockIdx.x * 8 + warp; n < M; n += gridDim.x * 8) {
        float acc[16];
        #pragma unroll
        for (int c = 0; c < 16; c++) acc[c] = 0.f;
        const float* hp = h + (size_t)n * 256;
        #pragma unroll
        for (int it = 0; it < 8; it++) {
            int k = lane + it * 32;
            float hv = hp[k];
            const float* wk = &Ws[k * 17];
            #pragma unroll
            for (int c = 0; c < 16; c++) acc[c] += hv * wk[c];
        }
        #pragma unroll
        for (int c = 0; c < 16; c++) {
            #pragma unroll
            for (int off = 16; off > 0; off >>= 1)
                acc[c] += __shfl_xor_sync(0xFFFFFFFFu, acc[c], off);
        }
        float l[16];
        float mx = -3.402823e38f;
        #pragma unroll
        for (int c = 0; c < 16; c++) { l[c] = acc[c] + Bsm[c]; mx = fmaxf(mx, l[c]); }
        float se = 0.f;
        #pragma unroll
        for (int c = 0; c < 16; c++) se += expf(l[c] - mx);
        float lse = mx + logf(se);
        if (lane < 16) out[(size_t)n * 16 + lane] = l[lane] - lse;
    }
}

// ----------------------------------------------------------------------------
// Launch
// ----------------------------------------------------------------------------
static void* sym(const void* s) {
    void* p = nullptr;
    cudaGetSymbolAddress(&p, s);
    return p;
}

extern "C" void kernel_launch(void* const* d_in, const int* in_sizes, int n_in,
                              void* d_out, int out_size) {
    const float* x        = (const float*)d_in[0];
    const int*   ei       = (const int*)  d_in[1];
    const float* ew       = (const float*)d_in[2];
    const float* pre_w0   = (const float*)d_in[3];
    const float* pre_b0   = (const float*)d_in[4];
    const float* arma_w0  = (const float*)d_in[5];
    const float* arma_v0  = (const float*)d_in[6];
    const float* arma_b0  = (const float*)d_in[7];
    const float* sage_wl0 = (const float*)d_in[8];
    const float* sage_bl0 = (const float*)d_in[9];
    const float* sage_wr0 = (const float*)d_in[10];
    const float* pre_w1   = (const float*)d_in[11];
    const float* pre_b1   = (const float*)d_in[12];
    const float* arma_w1  = (const float*)d_in[13];
    const float* arma_v1  = (const float*)d_in[14];
    const float* arma_b1  = (const float*)d_in[15];
    const float* sage_wl1 = (const float*)d_in[16];
    const float* sage_bl1 = (const float*)d_in[17];
    const float* sage_wr1 = (const float*)d_in[18];
    const float* cls_w    = (const float*)d_in[19];
    const float* cls_b    = (const float*)d_in[20];
    float* out = (float*)d_out;

    const int* row = ei;
    const int* col = ei + EE;

    float*  ph    = (float*) sym(g_h);
    float*  pu    = (float*) sym(g_u);
    float*  pr    = (float*) sym(g_r);
    __nv_bfloat16* ptb = (__nv_bfloat16*)sym(g_tb);
    __nv_bfloat16* psb = (__nv_bfloat16*)sym(g_sb);
    float*  pdeg  = (float*) sym(g_deg);
    int*    pcnti = (int*)   sym(g_cnti);
    int*    pcur  = (int*)   sym(g_cur);
    int*    poff  = (int*)   sym(g_off);
    int*    pblk  = (int*)   sym(g_blksum);
    float*  pdinv = (float*) sym(g_dinv);
    float*  picnt = (float*) sym(g_icnt);
    int*    pssrc = (int*)   sym(g_ssrc);
    float2* pscoef= (float2*)sym(g_scoef);
    float* pWt = (float*)sym(g_Wt); float* pWs = (float*)sym(g_Ws);
    float* pWu = (float*)sym(g_Wu); float* pWr = (float*)sym(g_Wr);
    float* pbt = (float*)sym(g_bt); float* pbs = (float*)sym(g_bs);
    float* pbu = (float*)sym(g_bu); float* pbr = (float*)sym(g_br);

    const int M = NN;
    const int MB = (M + 127) / 128;

    // ---- CSR build (once per call; shared by both cells) ----
    init_counts_kernel<<<(NN + 255) / 256, 256>>>(pdeg, pcnti, pcur, NN);
    hist_kernel<<<(EE + 255) / 256, 256>>>(col, ew, pdeg, pcnti, EE);
    dinv_kernel<<<(NN + 255) / 256, 256>>>(pdeg, pcnti, pdinv, picnt, NN);
    scan1_kernel<<<NBLK, SCAN_B>>>(pcnti, poff, pblk, NN);
    scan2_kernel<<<1, SCAN_B>>>(pblk, NBLK);
    scan3_kernel<<<(NN + 255) / 256, 256>>>(poff, pblk, NN, EE);
    edge_sort_kernel<<<(EE + 255) / 256, 256>>>(row, col, ew, poff, pcur,
                                                pdinv, picnt, pssrc, pscoef, EE);

    const float* cell_in = x;
    int cell_K = 128;

    const float* PW[2]  = {pre_w0, pre_w1};
    const float* PB[2]  = {pre_b0, pre_b1};
    const float* AW[2]  = {arma_w0, arma_w1};
    const float* AV[2]  = {arma_v0, arma_v1};
    const float* AB[2]  = {arma_b0, arma_b1};
    const float* SWL[2] = {sage_wl0, sage_wl1};
    const float* SBL[2] = {sage_bl0, sage_bl1};
    const float* SWR[2] = {sage_wr0, sage_wr1};

    const int agg_blocks = (NN * 32 + 255) / 256;

    for (int c = 0; c < 2; c++) {
        // compose: Wt = pre_w@arma_w ; Ws = pre_w@sage_wl ; Wu = pre_w@arma_v ;
        //          Wr = pre_w@sage_wr   (+ matching bias compositions)
        compose_w_kernel<<<dim3(cell_K * 128 / 256, 4), 256>>>(
            PW[c], cell_K, AW[c], SWL[c], AV[c], SWR[c], pWt, pWs, pWu, pWr);
        compose_b_kernel<<<1, 512>>>(PB[c], AW[c], SWL[c], AV[c], SWR[c],
                                     AB[c], SBL[c], pbt, pbs, pbu, pbr);

        // quad GEMM from cell input: t(bf16), s2(bf16), u(fp32), r(fp32)
        quad_gemm_kernel<<<dim3(MB, 4), 256>>>(
            cell_in, cell_K, pWt, pWs, pWu, pWr, pbt, pbs, pbu, pbr,
            ptb, psb, pu, pr, M, cell_K);

        // fused aggregation + cell epilogue -> h
        agg_epi_kernel<<<agg_blocks, 256>>>(poff, pssrc, pscoef, ptb, psb,
                                            pu, pr, ph, NN);

        cell_in = ph;
        cell_K = 256;
    }

    // classifier + log_softmax
    cls_kernel<<<(M + 7) / 8, 256>>>(ph, cls_w, cls_b, out, M);
}